// round 7
// baseline (speedup 1.0000x reference)
#include <cuda_runtime.h>
#include <cuda_bf16.h>
#include <math.h>
#include <stdint.h>

#define Bsz 2
#define Sq 2048
#define DM 1024
#define Hh 16
#define HDv 64
#define Mrows (Bsz*Sq)   /* 4096 */

#define QSCALE 0.18033688011112042f   /* 0.125 * log2(e) */

// ---------------- scratch (device globals; no allocs allowed) ----------------
__device__ __nv_bfloat16 g_xh[Mrows*DM];
__device__ __nv_bfloat16 g_xl[Mrows*DM];
__device__ __nv_bfloat16 g_qh[Mrows*DM];
__device__ __nv_bfloat16 g_ql[Mrows*DM];
__device__ __nv_bfloat16 g_kh[Mrows*DM];
__device__ __nv_bfloat16 g_kl[Mrows*DM];
__device__ __nv_bfloat16 g_vh[Mrows*DM];
__device__ __nv_bfloat16 g_vl[Mrows*DM];
__device__ __nv_bfloat16 g_ch[Mrows*DM];
__device__ __nv_bfloat16 g_cl[Mrows*DM];
__device__ __nv_bfloat16 g_wth[4*DM*DM];   // W^T split-hi, [N][K], order q,k,v,o
__device__ __nv_bfloat16 g_wtl[4*DM*DM];   // W^T split-lo

// ---------------- helpers ----------------
__device__ __forceinline__ uint32_t smem_u32(const void* p) {
    uint32_t a;
    asm("{ .reg .u64 t; cvta.to.shared.u64 t, %1; cvt.u32.u64 %0, t; }" : "=r"(a) : "l"(p));
    return a;
}
__device__ __forceinline__ void ldsm4(uint32_t* r, uint32_t addr) {
    asm volatile("ldmatrix.sync.aligned.m8n8.x4.shared.b16 {%0,%1,%2,%3}, [%4];"
                 : "=r"(r[0]), "=r"(r[1]), "=r"(r[2]), "=r"(r[3]) : "r"(addr));
}
__device__ __forceinline__ void ldsm4t(uint32_t* r, uint32_t addr) {
    asm volatile("ldmatrix.sync.aligned.m8n8.x4.trans.shared.b16 {%0,%1,%2,%3}, [%4];"
                 : "=r"(r[0]), "=r"(r[1]), "=r"(r[2]), "=r"(r[3]) : "r"(addr));
}
__device__ __forceinline__ void mma16816(float* c, const uint32_t* a, uint32_t b0, uint32_t b1) {
    asm volatile("mma.sync.aligned.m16n8k16.row.col.f32.bf16.bf16.f32 "
                 "{%0,%1,%2,%3}, {%4,%5,%6,%7}, {%8,%9}, {%0,%1,%2,%3};"
                 : "+f"(c[0]), "+f"(c[1]), "+f"(c[2]), "+f"(c[3])
                 : "r"(a[0]), "r"(a[1]), "r"(a[2]), "r"(a[3]), "r"(b0), "r"(b1));
}
#define CP_COMMIT() asm volatile("cp.async.commit_group;" ::: "memory")
#define CP_WAIT0()  asm volatile("cp.async.wait_group 0;" ::: "memory")
#define CP16(dst, src) asm volatile("cp.async.cg.shared.global [%0], [%1], 16;" :: "r"(dst), "l"(src) : "memory")

__device__ __forceinline__ uint32_t packbf2(float x, float y) {
    __nv_bfloat162 t = __floats2bfloat162_rn(x, y);
    return *(uint32_t*)&t;
}
// split a pair of floats into bf16 hi + bf16 lo packed regs
__device__ __forceinline__ void split2(float x, float y, uint32_t& h, uint32_t& l) {
    __nv_bfloat16 hx = __float2bfloat16(x), hy = __float2bfloat16(y);
    __nv_bfloat162 hh; hh.x = hx; hh.y = hy;
    h = *(uint32_t*)&hh;
    l = packbf2(x - __bfloat162float(hx), y - __bfloat162float(hy));
}
// fast exp2 for x <= 0: magic round + degree-5 Taylor (err ~3e-6); FFMA pipe only
__device__ __forceinline__ float exp2p(float x) {
    x = fmaxf(x, -60.0f);
    float r = x + 12582912.0f;
    int n = __float_as_int(r) - 0x4B400000;
    float f = x - (r - 12582912.0f);
    float p = 1.3333558e-3f;
    p = fmaf(p, f, 9.6181291e-3f);
    p = fmaf(p, f, 5.5504109e-2f);
    p = fmaf(p, f, 2.4022651e-1f);
    p = fmaf(p, f, 6.9314718e-1f);
    p = fmaf(p, f, 1.0f);
    return __int_as_float(__float_as_int(p) + (n << 23));
}

// ---------------- fp32 -> bf16 hi/lo split (elementwise) ----------------
__global__ __launch_bounds__(256) void fsplit_kernel(
    const float* __restrict__ src, __nv_bfloat16* __restrict__ h,
    __nv_bfloat16* __restrict__ l, int n4)
{
    int idx = blockIdx.x * 256 + threadIdx.x;
    if (idx >= n4) return;
    float4 v = ((const float4*)src)[idx];
    uint32_t h0, l0, h1, l1;
    split2(v.x, v.y, h0, l0);
    split2(v.z, v.w, h1, l1);
    ((uint32_t*)h)[idx * 2 + 0] = h0;
    ((uint32_t*)h)[idx * 2 + 1] = h1;
    ((uint32_t*)l)[idx * 2 + 0] = l0;
    ((uint32_t*)l)[idx * 2 + 1] = l1;
}

// ---------------- W[K][N] fp32 -> W^T[N][K] bf16 hi/lo ----------------
__global__ __launch_bounds__(256) void wsplit_kernel(
    const float* __restrict__ W0, const float* __restrict__ W1,
    const float* __restrict__ W2, const float* __restrict__ W3,
    __nv_bfloat16* __restrict__ oh, __nv_bfloat16* __restrict__ ol)
{
    __shared__ float t[32][33];
    int z = blockIdx.z;
    const float* W = (z == 0) ? W0 : (z == 1) ? W1 : (z == 2) ? W2 : W3;
    size_t zoff = (size_t)z * DM * DM;
    int bn = blockIdx.x * 32;
    int bk = blockIdx.y * 32;
    int tx = threadIdx.x & 31;
    int ty = threadIdx.x >> 5;
#pragma unroll
    for (int r = 0; r < 4; r++)
        t[ty + 8 * r][tx] = W[(size_t)(bk + ty + 8 * r) * DM + bn + tx];
    __syncthreads();
#pragma unroll
    for (int r = 0; r < 4; r++) {
        int nl = ty + 8 * r;
        float v = t[tx][nl];
        __nv_bfloat16 h = __float2bfloat16(v);
        __nv_bfloat16 l = __float2bfloat16(v - __bfloat162float(h));
        oh[zoff + (size_t)(bn + nl) * DM + bk + tx] = h;
        ol[zoff + (size_t)(bn + nl) * DM + bk + tx] = l;
    }
}

// ---------------- HMMA bf16-split GEMM ----------------
// C[4096,1024] = A[M,K] @ B^T (B stored [N,K] K-major).
// Block tile 128x128, BK=64, 8 warps (warp tile 32x64), 2 blocks/SM.
// SMEM 96KB: A hi/lo double-buffered (2x32KB stages), B hi/lo single (32KB).
// 3 split terms: AhBh + AhBl + AlBh.
#define HTILE 16384                    /* 128 rows x 64 bf16 */
#define GA_STAGE (2 * HTILE)           /* Ah + Al per stage = 32KB */
#define GB_OFF   (2 * GA_STAGE)        /* B area at 64KB */
#define GEMM_SMEM (GB_OFF + 2 * HTILE) /* 96KB */

__device__ __forceinline__ void load_tile64(uint32_t sdst, const __nv_bfloat16* g, int tid) {
#pragma unroll
    for (int i = 0; i < 4; i++) {
        int f = i * 256 + tid;
        int r = f >> 3;
        int q = f & 7;
        uint32_t byte = (uint32_t)(r * 128 + q * 16);
        byte ^= ((byte >> 3) & 0x70);
        CP16(sdst + byte, g + (size_t)r * DM + q * 8);
    }
}

template<bool SPLIT>
__global__ __launch_bounds__(256, 2) void gemm_hmma_kernel(
    const __nv_bfloat16* __restrict__ Ah, const __nv_bfloat16* __restrict__ Al,
    const __nv_bfloat16* __restrict__ Bh_base, const __nv_bfloat16* __restrict__ Bl_base,
    __nv_bfloat16* H0, __nv_bfloat16* L0,
    __nv_bfloat16* H1, __nv_bfloat16* L1,
    __nv_bfloat16* H2, __nv_bfloat16* L2,
    float* __restrict__ Cf, const float* __restrict__ bias)
{
    extern __shared__ __align__(1024) char sm[];
    const int tid = threadIdx.x;
    const int wid = tid >> 5;
    const int lane = tid & 31;
    const int z = blockIdx.z;
    const int colBase = blockIdx.x * 128;
    const int rowBase = blockIdx.y * 128;
    const int wm = (wid & 3) * 32;   // warp M offset
    const int wn = (wid >> 2) * 64;  // warp N offset

    const uint32_t sbase = smem_u32(sm);
    const __nv_bfloat16* agh = Ah + (size_t)rowBase * DM;
    const __nv_bfloat16* agl = Al + (size_t)rowBase * DM;
    const __nv_bfloat16* bgh = Bh_base + (size_t)z * DM * DM + (size_t)colBase * DM;
    const __nv_bfloat16* bgl = Bl_base + (size_t)z * DM * DM + (size_t)colBase * DM;

    float acc[2][8][4];
#pragma unroll
    for (int mi = 0; mi < 2; mi++)
#pragma unroll
        for (int nj = 0; nj < 8; nj++)
#pragma unroll
            for (int r = 0; r < 4; r++) acc[mi][nj][r] = 0.f;

    // hoisted swizzled address bases
    const int lrow = lane & 15;
    const int lquad = (lane >> 4) << 4;
    const uint32_t swz = (uint32_t)((lrow & 7) << 4);
    uint32_t koff[4], arow[2], brow[4];
#pragma unroll
    for (int ks = 0; ks < 4; ks++) koff[ks] = ((uint32_t)(ks * 32 + lquad)) ^ swz;
#pragma unroll
    for (int i = 0; i < 2; i++) arow[i] = (uint32_t)((wm + i * 16 + lrow) * 128);
#pragma unroll
    for (int i = 0; i < 4; i++) brow[i] = (uint32_t)((wn + i * 16 + lrow) * 128);

    // prologue: A0 into stage 0, B0 into B area
    load_tile64(sbase,          agh, tid);
    load_tile64(sbase + HTILE,  agl, tid);
    load_tile64(sbase + GB_OFF,         bgh, tid);
    load_tile64(sbase + GB_OFF + HTILE, bgl, tid);
    CP_COMMIT();

    const int NCHUNK = DM / 64;  // 16

    for (int c = 0; c < NCHUNK; c++) {
        CP_WAIT0();
        __syncthreads();
        const uint32_t Ab = sbase + (uint32_t)(c & 1) * GA_STAGE;

        // prefetch next A (overlaps compute)
        if (c + 1 < NCHUNK) {
            const uint32_t nst = sbase + (uint32_t)((c + 1) & 1) * GA_STAGE;
            const int k0 = (c + 1) * 64;
            load_tile64(nst,         agh + k0, tid);
            load_tile64(nst + HTILE, agl + k0, tid);
            CP_COMMIT();
        }

#pragma unroll
        for (int ks = 0; ks < 4; ks++) {
            const uint32_t ko = koff[ks];
            uint32_t ah[2][4], al[2][4];
#pragma unroll
            for (int mi = 0; mi < 2; mi++) {
                ldsm4(ah[mi], Ab + arow[mi] + ko);
                ldsm4(al[mi], Ab + HTILE + arow[mi] + ko);
            }
#pragma unroll
            for (int ni = 0; ni < 4; ni++) {
                uint32_t bh[4], bl[4];
                ldsm4(bh, sbase + GB_OFF + brow[ni] + ko);
                ldsm4(bl, sbase + GB_OFF + HTILE + brow[ni] + ko);
#pragma unroll
                for (int mi = 0; mi < 2; mi++) {
#pragma unroll
                    for (int s = 0; s < 2; s++) {
                        float* a = acc[mi][ni * 2 + s];
                        mma16816(a, ah[mi], bh[s], bh[s + 2]);
                        mma16816(a, ah[mi], bl[s], bl[s + 2]);
                        mma16816(a, al[mi], bh[s], bh[s + 2]);
                    }
                }
            }
        }
        __syncthreads();   // everyone done reading B[c]

        // load next B (bubble covered by co-resident block)
        if (c + 1 < NCHUNK) {
            const int k0 = (c + 1) * 64;
            load_tile64(sbase + GB_OFF,         bgh + k0, tid);
            load_tile64(sbase + GB_OFF + HTILE, bgl + k0, tid);
            CP_COMMIT();
        }
    }

    // ---- epilogue ----
    if (SPLIT) {
        __nv_bfloat16* H = (z == 0) ? H0 : (z == 1) ? H1 : H2;
        __nv_bfloat16* L = (z == 0) ? L0 : (z == 1) ? L1 : L2;
        const float sc = (z == 0) ? QSCALE : 1.0f;
#pragma unroll
        for (int mi = 0; mi < 2; mi++) {
            const int r0 = rowBase + wm + mi * 16 + (lane >> 2);
#pragma unroll
            for (int nj = 0; nj < 8; nj++) {
                const int col = colBase + wn + nj * 8 + (lane & 3) * 2;
                uint32_t h0, l0, h1, l1;
                split2(acc[mi][nj][0] * sc, acc[mi][nj][1] * sc, h0, l0);
                split2(acc[mi][nj][2] * sc, acc[mi][nj][3] * sc, h1, l1);
                *(uint32_t*)(H + (size_t)r0 * DM + col) = h0;
                *(uint32_t*)(L + (size_t)r0 * DM + col) = l0;
                *(uint32_t*)(H + (size_t)(r0 + 8) * DM + col) = h1;
                *(uint32_t*)(L + (size_t)(r0 + 8) * DM + col) = l1;
            }
        }
    } else {
#pragma unroll
        for (int mi = 0; mi < 2; mi++) {
            const int r0 = rowBase + wm + mi * 16 + (lane >> 2);
#pragma unroll
            for (int nj = 0; nj < 8; nj++) {
                const int col = colBase + wn + nj * 8 + (lane & 3) * 2;
                float2 bb = *(const float2*)(bias + col);
                float2 v0 = make_float2(acc[mi][nj][0] + bb.x, acc[mi][nj][1] + bb.y);
                float2 v1 = make_float2(acc[mi][nj][2] + bb.x, acc[mi][nj][3] + bb.y);
                *(float2*)(Cf + (size_t)r0 * DM + col) = v0;
                *(float2*)(Cf + (size_t)(r0 + 8) * DM + col) = v1;
            }
        }
    }
}

// ---------------- HMMA causal flash attention ----------------
// Block: 256 thr (8 warps), 128 queries x 64-key tiles, 2 blocks/SM.
// Q tile persistent in SMEM (32KB, re-ldsm per k-step, frees 32 regs);
// KV double-buffered (2 x 32KB stages). SMEM total 96KB.
// S = QhKh + QhKl + QlKh; softmax via FFMA exp2 poly; O += PhVh + PhVl + PlVh.
#define AT_KV0   32768
#define AT_STAGE 32768
#define AT_SMEM  (AT_KV0 + 2 * AT_STAGE)   /* 96KB */

__device__ __forceinline__ void load_kv_tiles(
    uint32_t sdst, const __nv_bfloat16* kh, const __nv_bfloat16* kl,
    const __nv_bfloat16* vh, const __nv_bfloat16* vl, int tid)
{
#pragma unroll
    for (int i = 0; i < 2; i++) {
        int f = i * 256 + tid;
        int r = f >> 3;
        int q = f & 7;
        uint32_t byte = (uint32_t)(r * 128 + q * 16);
        byte ^= ((byte >> 3) & 0x70);
        size_t go = (size_t)r * DM + q * 8;
        CP16(sdst + byte,         kh + go);
        CP16(sdst + 8192 + byte,  kl + go);
        CP16(sdst + 16384 + byte, vh + go);
        CP16(sdst + 24576 + byte, vl + go);
    }
}

__global__ __launch_bounds__(256, 2) void attn_mma_kernel(
    const __nv_bfloat16* __restrict__ Qh, const __nv_bfloat16* __restrict__ Ql,
    const __nv_bfloat16* __restrict__ Kh, const __nv_bfloat16* __restrict__ Kl,
    const __nv_bfloat16* __restrict__ Vh, const __nv_bfloat16* __restrict__ Vl,
    __nv_bfloat16* __restrict__ Ch, __nv_bfloat16* __restrict__ Cl)
{
    extern __shared__ __align__(1024) char sm[];
    const uint32_t sb = smem_u32(sm);
    const int tid = threadIdx.x;
    const int wid = tid >> 5;
    const int lane = tid & 31;
    const int mblk = (int)gridDim.x - 1 - (int)blockIdx.x;  // heavy-first
    const int bh = blockIdx.y;
    const int b = bh >> 4;
    const int h = bh & 15;
    const size_t headoff = (size_t)(b * Sq) * DM + h * HDv;
    const int wrow = wid * 16;
    const int lrow = lane & 15;
    const int lq = (lane >> 4) * 16;

    // hoisted swizzled address pieces
    const uint32_t swz = (uint32_t)((lrow & 7) << 4);
    uint32_t koff[4], rowb[4];
#pragma unroll
    for (int j = 0; j < 4; j++) {
        koff[j] = ((uint32_t)(j * 32 + lq)) ^ swz;
        rowb[j] = (uint32_t)((j * 16 + lrow) * 128);
    }
    const uint32_t qrow = (uint32_t)((wrow + lrow) * 128);

    // ---- prologue: stage Q tile (persistent) + KV tile 0, one commit ----
    const __nv_bfloat16* qgh = Qh + headoff + (size_t)(mblk * 128) * DM;
    const __nv_bfloat16* qgl = Ql + headoff + (size_t)(mblk * 128) * DM;
#pragma unroll
    for (int i = 0; i < 4; i++) {
        int f = i * 256 + tid;
        int r = f >> 3;
        int q = f & 7;
        uint32_t byte = (uint32_t)(r * 128 + q * 16);
        byte ^= ((byte >> 3) & 0x70);
        size_t go = (size_t)r * DM + q * 8;
        CP16(sb + byte, qgh + go);
        CP16(sb + 16384 + byte, qgl + go);
    }
    const __nv_bfloat16* kgh = Kh + headoff;
    const __nv_bfloat16* kgl = Kl + headoff;
    const __nv_bfloat16* vgh = Vh + headoff;
    const __nv_bfloat16* vgl = Vl + headoff;
    load_kv_tiles(sb + AT_KV0, kgh, kgl, vgh, vgl, tid);
    CP_COMMIT();

    float Oacc[8][4];
#pragma unroll
    for (int nj = 0; nj < 8; nj++)
#pragma unroll
        for (int r = 0; r < 4; r++) Oacc[nj][r] = 0.f;
    float m0 = -INFINITY, m1 = -INFINITY, l0 = 0.f, l1 = 0.f;

    const int ntiles = 2 * mblk + 2;

    for (int t = 0; t < ntiles; t++) {
        CP_WAIT0();
        __syncthreads();
        const uint32_t cur = sb + AT_KV0 + (uint32_t)(t & 1) * AT_STAGE;

        if (t + 1 < ntiles) {
            const size_t off = (size_t)((t + 1) * 64) * DM;
            load_kv_tiles(sb + AT_KV0 + (uint32_t)((t + 1) & 1) * AT_STAGE,
                          kgh + off, kgl + off, vgh + off, vgl + off, tid);
            CP_COMMIT();
        }

        // ---- S = Q K^T (3 split terms; Q frags re-ldsm'd from persistent smem) ----
        float S[8][4];
#pragma unroll
        for (int nj = 0; nj < 8; nj++)
#pragma unroll
            for (int r = 0; r < 4; r++) S[nj][r] = 0.f;

#pragma unroll
        for (int ks = 0; ks < 4; ks++) {
            const uint32_t ko = koff[ks];
            uint32_t qfh[4], qfl[4];
            ldsm4(qfh, sb + qrow + ko);
            ldsm4(qfl, sb + 16384 + qrow + ko);
            uint32_t kf_h[4][4], kf_l[4][4];
#pragma unroll
            for (int ni = 0; ni < 4; ni++) {
                ldsm4(kf_h[ni], cur + rowb[ni] + ko);
                ldsm4(kf_l[ni], cur + 8192 + rowb[ni] + ko);
            }
#pragma unroll
            for (int nj = 0; nj < 8; nj++) {
                const int ni = nj >> 1, s = nj & 1;
                mma16816(S[nj], qfh, kf_h[ni][s], kf_h[ni][s + 2]);
                mma16816(S[nj], qfh, kf_l[ni][s], kf_l[ni][s + 2]);
                mma16816(S[nj], qfl, kf_h[ni][s], kf_h[ni][s + 2]);
            }
        }

        // ---- causal mask (last two tiles only) ----
        if (t >= ntiles - 2) {
            const int rg0 = mblk * 128 + wrow + (lane >> 2);
            const int rg1 = rg0 + 8;
            const int cb = t * 64 + (lane & 3) * 2;
#pragma unroll
            for (int nj = 0; nj < 8; nj++) {
                const int c0 = cb + nj * 8, c1 = c0 + 1;
                if (c0 > rg0) S[nj][0] = -1e30f;
                if (c1 > rg0) S[nj][1] = -1e30f;
                if (c0 > rg1) S[nj][2] = -1e30f;
                if (c1 > rg1) S[nj][3] = -1e30f;
            }
        }

        // ---- online softmax (exp2 poly on FFMA pipe) ----
        float mt0 = -INFINITY, mt1 = -INFINITY;
#pragma unroll
        for (int nj = 0; nj < 8; nj++) {
            mt0 = fmaxf(mt0, fmaxf(S[nj][0], S[nj][1]));
            mt1 = fmaxf(mt1, fmaxf(S[nj][2], S[nj][3]));
        }
        mt0 = fmaxf(mt0, __shfl_xor_sync(0xffffffffu, mt0, 1));
        mt0 = fmaxf(mt0, __shfl_xor_sync(0xffffffffu, mt0, 2));
        mt1 = fmaxf(mt1, __shfl_xor_sync(0xffffffffu, mt1, 1));
        mt1 = fmaxf(mt1, __shfl_xor_sync(0xffffffffu, mt1, 2));
        const float mn0 = fmaxf(m0, mt0), mn1 = fmaxf(m1, mt1);
        const float a0 = exp2p(m0 - mn0), a1 = exp2p(m1 - mn1);
        m0 = mn0; m1 = mn1;
        l0 *= a0; l1 *= a1;
        float rs0 = 0.f, rs1 = 0.f;
#pragma unroll
        for (int nj = 0; nj < 8; nj++) {
            Oacc[nj][0] *= a0; Oacc[nj][1] *= a0;
            Oacc[nj][2] *= a1; Oacc[nj][3] *= a1;
            S[nj][0] = exp2p(S[nj][0] - mn0);
            S[nj][1] = exp2p(S[nj][1] - mn0);
            S[nj][2] = exp2p(S[nj][2] - mn1);
            S[nj][3] = exp2p(S[nj][3] - mn1);
            rs0 += S[nj][0] + S[nj][1];
            rs1 += S[nj][2] + S[nj][3];
        }
        l0 += rs0; l1 += rs1;

        // ---- O += P V (3 split terms; V^T via ldmatrix.trans) ----
#pragma unroll
        for (int kk = 0; kk < 4; kk++) {
            uint32_t pah[4], pal[4];
            split2(S[2 * kk][0],     S[2 * kk][1],     pah[0], pal[0]);
            split2(S[2 * kk][2],     S[2 * kk][3],     pah[1], pal[1]);
            split2(S[2 * kk + 1][0], S[2 * kk + 1][1], pah[2], pal[2]);
            split2(S[2 * kk + 1][2], S[2 * kk + 1][3], pah[3], pal[3]);
#pragma unroll
            for (int dp = 0; dp < 4; dp++) {
                const uint32_t vb = cur + rowb[kk] + koff[dp];
                uint32_t vfh[4], vfl[4];
                ldsm4t(vfh, vb + 16384);
                ldsm4t(vfl, vb + 24576);
                mma16816(Oacc[2 * dp], pah, vfh[0], vfh[1]);
                mma16816(Oacc[2 * dp], pah, vfl[0], vfl[1]);
                mma16816(Oacc[2 * dp], pal, vfh[0], vfh[1]);
                mma16816(Oacc[2 * dp + 1], pah, vfh[2], vfh[3]);
                mma16816(Oacc[2 * dp + 1], pah, vfl[2], vfl[3]);
                mma16816(Oacc[2 * dp + 1], pal, vfh[2], vfh[3]);
            }
        }
    }

    // ---- epilogue ----
    l0 += __shfl_xor_sync(0xffffffffu, l0, 1);
    l0 += __shfl_xor_sync(0xffffffffu, l0, 2);
    l1 += __shfl_xor_sync(0xffffffffu, l1, 1);
    l1 += __shfl_xor_sync(0xffffffffu, l1, 2);
    const float inv0 = 1.f / l0, inv1 = 1.f / l1;
    const size_t tok0 = (size_t)(b * Sq + mblk * 128 + wrow + (lane >> 2));
    const size_t tok1 = tok0 + 8;
    const int colb = h * HDv + (lane & 3) * 2;
#pragma unroll
    for (int nj = 0; nj < 8; nj++) {
        const int col = colb + nj * 8;
        uint32_t h0, lo0, h1, lo1;
        split2(Oacc[nj][0] * inv0, Oacc[nj][1] * inv0, h0, lo0);
        split2(Oacc[nj][2] * inv1, Oacc[nj][3] * inv1, h1, lo1);
        *(uint32_t*)(Ch + tok0 * DM + col) = h0;
        *(uint32_t*)(Cl + tok0 * DM + col) = lo0;
        *(uint32_t*)(Ch + tok1 * DM + col) = h1;
        *(uint32_t*)(Cl + tok1 * DM + col) = lo1;
    }
}

// ---------------------------------------------------------------------------
extern "C" void kernel_launch(void* const* d_in, const int* in_sizes, int n_in,
                              void* d_out, int out_size)
{
    const float* x  = (const float*)d_in[0];
    const float* Wq = (const float*)d_in[1];
    const float* Wk = (const float*)d_in[2];
    const float* Wv = (const float*)d_in[3];
    const float* Wo = (const float*)d_in[4];
    const float* bo = (const float*)d_in[5];
    float* out = (float*)d_out;

    __nv_bfloat16 *xh, *xl, *qh, *ql, *kh, *kl, *vh, *vl, *ch, *cl, *wth, *wtl;
    cudaGetSymbolAddress((void**)&xh, g_xh);
    cudaGetSymbolAddress((void**)&xl, g_xl);
    cudaGetSymbolAddress((void**)&qh, g_qh);
    cudaGetSymbolAddress((void**)&ql, g_ql);
    cudaGetSymbolAddress((void**)&kh, g_kh);
    cudaGetSymbolAddress((void**)&kl, g_kl);
    cudaGetSymbolAddress((void**)&vh, g_vh);
    cudaGetSymbolAddress((void**)&vl, g_vl);
    cudaGetSymbolAddress((void**)&ch, g_ch);
    cudaGetSymbolAddress((void**)&cl, g_cl);
    cudaGetSymbolAddress((void**)&wth, g_wth);
    cudaGetSymbolAddress((void**)&wtl, g_wtl);

    static int attr_set = 0;
    if (!attr_set) {
        cudaFuncSetAttribute(gemm_hmma_kernel<true>,
                             cudaFuncAttributeMaxDynamicSharedMemorySize, GEMM_SMEM);
        cudaFuncSetAttribute(gemm_hmma_kernel<false>,
                             cudaFuncAttributeMaxDynamicSharedMemorySize, GEMM_SMEM);
        cudaFuncSetAttribute(attn_mma_kernel,
                             cudaFuncAttributeMaxDynamicSharedMemorySize, AT_SMEM);
        attr_set = 1;
    }

    const int n4 = Mrows * DM / 4;
    fsplit_kernel<<<(n4 + 255) / 256, 256>>>(x, xh, xl, n4);
    wsplit_kernel<<<dim3(32, 32, 4), 256>>>(Wq, Wk, Wv, Wo, wth, wtl);

    // QKV projections -> split bf16 outputs (Q pre-scaled by 0.125*log2e)
    gemm_hmma_kernel<true><<<dim3(DM / 128, Mrows / 128, 3), 256, GEMM_SMEM>>>(
        xh, xl, wth, wtl, qh, ql, kh, kl, vh, vl, nullptr, nullptr);

    attn_mma_kernel<<<dim3(Sq / 128, Bsz * Hh), 256, AT_SMEM>>>(
        qh, ql, kh, kl, vh, vl, ch, cl);

    // output projection (+bias)
    gemm_hmma_kernel<false><<<dim3(DM / 128, Mrows / 128, 1), 256, GEMM_SMEM>>>(
        ch, cl, wth + (size_t)3 * DM * DM, wtl + (size_t)3 * DM * DM,
        nullptr, nullptr, nullptr, nullptr, nullptr, nullptr, out, bo);
}

// round 8
// speedup vs baseline: 1.0426x; 1.0426x over previous
#include <cuda_runtime.h>
#include <cuda_bf16.h>
#include <math.h>
#include <stdint.h>

#define Bsz 2
#define Sq 2048
#define DM 1024
#define Hh 16
#define HDv 64
#define Mrows (Bsz*Sq)   /* 4096 */

#define QSCALE 0.18033688011112042f   /* 0.125 * log2(e) */

// ---------------- scratch (device globals; no allocs allowed) ----------------
__device__ __nv_bfloat16 g_xh[Mrows*DM];
__device__ __nv_bfloat16 g_xl[Mrows*DM];
__device__ __nv_bfloat16 g_qh[Mrows*DM];
__device__ __nv_bfloat16 g_ql[Mrows*DM];
__device__ __nv_bfloat16 g_kh[Mrows*DM];
__device__ __nv_bfloat16 g_kl[Mrows*DM];
__device__ __nv_bfloat16 g_vh[Mrows*DM];
__device__ __nv_bfloat16 g_vl[Mrows*DM];
__device__ __nv_bfloat16 g_ch[Mrows*DM];
__device__ __nv_bfloat16 g_cl[Mrows*DM];
__device__ __nv_bfloat16 g_wth[4*DM*DM];   // W^T split-hi, [N][K], order q,k,v,o
__device__ __nv_bfloat16 g_wtl[4*DM*DM];   // W^T split-lo

// ---------------- helpers ----------------
__device__ __forceinline__ uint32_t smem_u32(const void* p) {
    uint32_t a;
    asm("{ .reg .u64 t; cvta.to.shared.u64 t, %1; cvt.u32.u64 %0, t; }" : "=r"(a) : "l"(p));
    return a;
}
__device__ __forceinline__ void ldsm4(uint32_t* r, uint32_t addr) {
    asm volatile("ldmatrix.sync.aligned.m8n8.x4.shared.b16 {%0,%1,%2,%3}, [%4];"
                 : "=r"(r[0]), "=r"(r[1]), "=r"(r[2]), "=r"(r[3]) : "r"(addr));
}
__device__ __forceinline__ void ldsm4t(uint32_t* r, uint32_t addr) {
    asm volatile("ldmatrix.sync.aligned.m8n8.x4.trans.shared.b16 {%0,%1,%2,%3}, [%4];"
                 : "=r"(r[0]), "=r"(r[1]), "=r"(r[2]), "=r"(r[3]) : "r"(addr));
}
__device__ __forceinline__ void mma16816(float* c, const uint32_t* a, uint32_t b0, uint32_t b1) {
    asm volatile("mma.sync.aligned.m16n8k16.row.col.f32.bf16.bf16.f32 "
                 "{%0,%1,%2,%3}, {%4,%5,%6,%7}, {%8,%9}, {%0,%1,%2,%3};"
                 : "+f"(c[0]), "+f"(c[1]), "+f"(c[2]), "+f"(c[3])
                 : "r"(a[0]), "r"(a[1]), "r"(a[2]), "r"(a[3]), "r"(b0), "r"(b1));
}
#define CP_COMMIT() asm volatile("cp.async.commit_group;" ::: "memory")
#define CP_WAIT0()  asm volatile("cp.async.wait_group 0;" ::: "memory")
#define CP16(dst, src) asm volatile("cp.async.cg.shared.global [%0], [%1], 16;" :: "r"(dst), "l"(src) : "memory")

__device__ __forceinline__ uint32_t packbf2(float x, float y) {
    __nv_bfloat162 t = __floats2bfloat162_rn(x, y);
    return *(uint32_t*)&t;
}
// split a pair of floats into bf16 hi + bf16 lo packed regs
__device__ __forceinline__ void split2(float x, float y, uint32_t& h, uint32_t& l) {
    __nv_bfloat16 hx = __float2bfloat16(x), hy = __float2bfloat16(y);
    __nv_bfloat162 hh; hh.x = hx; hh.y = hy;
    h = *(uint32_t*)&hh;
    l = packbf2(x - __bfloat162float(hx), y - __bfloat162float(hy));
}
// fast exp2 for x <= 0: magic round + degree-5 Taylor (err ~3e-6); FFMA pipe only
__device__ __forceinline__ float exp2p(float x) {
    x = fmaxf(x, -60.0f);
    float r = x + 12582912.0f;
    int n = __float_as_int(r) - 0x4B400000;
    float f = x - (r - 12582912.0f);
    float p = 1.3333558e-3f;
    p = fmaf(p, f, 9.6181291e-3f);
    p = fmaf(p, f, 5.5504109e-2f);
    p = fmaf(p, f, 2.4022651e-1f);
    p = fmaf(p, f, 6.9314718e-1f);
    p = fmaf(p, f, 1.0f);
    return __int_as_float(__float_as_int(p) + (n << 23));
}

// ---------------- fp32 -> bf16 hi/lo split (elementwise) ----------------
__global__ __launch_bounds__(256) void fsplit_kernel(
    const float* __restrict__ src, __nv_bfloat16* __restrict__ h,
    __nv_bfloat16* __restrict__ l, int n4)
{
    int idx = blockIdx.x * 256 + threadIdx.x;
    if (idx >= n4) return;
    float4 v = ((const float4*)src)[idx];
    uint32_t h0, l0, h1, l1;
    split2(v.x, v.y, h0, l0);
    split2(v.z, v.w, h1, l1);
    ((uint32_t*)h)[idx * 2 + 0] = h0;
    ((uint32_t*)h)[idx * 2 + 1] = h1;
    ((uint32_t*)l)[idx * 2 + 0] = l0;
    ((uint32_t*)l)[idx * 2 + 1] = l1;
}

// ---------------- W[K][N] fp32 -> W^T[N][K] bf16 hi/lo ----------------
__global__ __launch_bounds__(256) void wsplit_kernel(
    const float* __restrict__ W0, const float* __restrict__ W1,
    const float* __restrict__ W2, const float* __restrict__ W3,
    __nv_bfloat16* __restrict__ oh, __nv_bfloat16* __restrict__ ol)
{
    __shared__ float t[32][33];
    int z = blockIdx.z;
    const float* W = (z == 0) ? W0 : (z == 1) ? W1 : (z == 2) ? W2 : W3;
    size_t zoff = (size_t)z * DM * DM;
    int bn = blockIdx.x * 32;
    int bk = blockIdx.y * 32;
    int tx = threadIdx.x & 31;
    int ty = threadIdx.x >> 5;
#pragma unroll
    for (int r = 0; r < 4; r++)
        t[ty + 8 * r][tx] = W[(size_t)(bk + ty + 8 * r) * DM + bn + tx];
    __syncthreads();
#pragma unroll
    for (int r = 0; r < 4; r++) {
        int nl = ty + 8 * r;
        float v = t[tx][nl];
        __nv_bfloat16 h = __float2bfloat16(v);
        __nv_bfloat16 l = __float2bfloat16(v - __bfloat162float(h));
        oh[zoff + (size_t)(bn + nl) * DM + bk + tx] = h;
        ol[zoff + (size_t)(bn + nl) * DM + bk + tx] = l;
    }
}

// ---------------- HMMA bf16-split GEMM (R7 config: 2 blocks/SM) ----------------
// C[4096,1024] = A[M,K] @ B^T (B stored [N,K] K-major).
// Block tile 128x128, BK=64, 8 warps (warp tile 32x64), 2 blocks/SM.
// SMEM 96KB: A hi/lo double-buffered (2x32KB stages), B hi/lo single (32KB).
// 3 split terms: AhBh + AhBl + AlBh.
#define HTILE 16384                    /* 128 rows x 64 bf16 */
#define GA_STAGE (2 * HTILE)           /* Ah + Al per stage = 32KB */
#define GB_OFF   (2 * GA_STAGE)        /* B area at 64KB */
#define GEMM_SMEM (GB_OFF + 2 * HTILE) /* 96KB */

__device__ __forceinline__ void load_tile64(uint32_t sdst, const __nv_bfloat16* g, int tid) {
#pragma unroll
    for (int i = 0; i < 4; i++) {
        int f = i * 256 + tid;
        int r = f >> 3;
        int q = f & 7;
        uint32_t byte = (uint32_t)(r * 128 + q * 16);
        byte ^= ((byte >> 3) & 0x70);
        CP16(sdst + byte, g + (size_t)r * DM + q * 8);
    }
}

template<bool SPLIT>
__global__ __launch_bounds__(256, 2) void gemm_hmma_kernel(
    const __nv_bfloat16* __restrict__ Ah, const __nv_bfloat16* __restrict__ Al,
    const __nv_bfloat16* __restrict__ Bh_base, const __nv_bfloat16* __restrict__ Bl_base,
    __nv_bfloat16* H0, __nv_bfloat16* L0,
    __nv_bfloat16* H1, __nv_bfloat16* L1,
    __nv_bfloat16* H2, __nv_bfloat16* L2,
    float* __restrict__ Cf, const float* __restrict__ bias)
{
    extern __shared__ __align__(1024) char sm[];
    const int tid = threadIdx.x;
    const int wid = tid >> 5;
    const int lane = tid & 31;
    const int z = blockIdx.z;
    const int colBase = blockIdx.x * 128;
    const int rowBase = blockIdx.y * 128;
    const int wm = (wid & 3) * 32;   // warp M offset
    const int wn = (wid >> 2) * 64;  // warp N offset

    const uint32_t sbase = smem_u32(sm);
    const __nv_bfloat16* agh = Ah + (size_t)rowBase * DM;
    const __nv_bfloat16* agl = Al + (size_t)rowBase * DM;
    const __nv_bfloat16* bgh = Bh_base + (size_t)z * DM * DM + (size_t)colBase * DM;
    const __nv_bfloat16* bgl = Bl_base + (size_t)z * DM * DM + (size_t)colBase * DM;

    float acc[2][8][4];
#pragma unroll
    for (int mi = 0; mi < 2; mi++)
#pragma unroll
        for (int nj = 0; nj < 8; nj++)
#pragma unroll
            for (int r = 0; r < 4; r++) acc[mi][nj][r] = 0.f;

    // hoisted swizzled address bases
    const int lrow = lane & 15;
    const int lquad = (lane >> 4) << 4;
    const uint32_t swz = (uint32_t)((lrow & 7) << 4);
    uint32_t koff[4], arow[2], brow[4];
#pragma unroll
    for (int ks = 0; ks < 4; ks++) koff[ks] = ((uint32_t)(ks * 32 + lquad)) ^ swz;
#pragma unroll
    for (int i = 0; i < 2; i++) arow[i] = (uint32_t)((wm + i * 16 + lrow) * 128);
#pragma unroll
    for (int i = 0; i < 4; i++) brow[i] = (uint32_t)((wn + i * 16 + lrow) * 128);

    // prologue: A0 into stage 0, B0 into B area
    load_tile64(sbase,          agh, tid);
    load_tile64(sbase + HTILE,  agl, tid);
    load_tile64(sbase + GB_OFF,         bgh, tid);
    load_tile64(sbase + GB_OFF + HTILE, bgl, tid);
    CP_COMMIT();

    const int NCHUNK = DM / 64;  // 16

    for (int c = 0; c < NCHUNK; c++) {
        CP_WAIT0();
        __syncthreads();
        const uint32_t Ab = sbase + (uint32_t)(c & 1) * GA_STAGE;

        // prefetch next A (overlaps compute)
        if (c + 1 < NCHUNK) {
            const uint32_t nst = sbase + (uint32_t)((c + 1) & 1) * GA_STAGE;
            const int k0 = (c + 1) * 64;
            load_tile64(nst,         agh + k0, tid);
            load_tile64(nst + HTILE, agl + k0, tid);
            CP_COMMIT();
        }

#pragma unroll
        for (int ks = 0; ks < 4; ks++) {
            const uint32_t ko = koff[ks];
            uint32_t ah[2][4], al[2][4];
#pragma unroll
            for (int mi = 0; mi < 2; mi++) {
                ldsm4(ah[mi], Ab + arow[mi] + ko);
                ldsm4(al[mi], Ab + HTILE + arow[mi] + ko);
            }
#pragma unroll
            for (int ni = 0; ni < 4; ni++) {
                uint32_t bh[4], bl[4];
                ldsm4(bh, sbase + GB_OFF + brow[ni] + ko);
                ldsm4(bl, sbase + GB_OFF + HTILE + brow[ni] + ko);
#pragma unroll
                for (int mi = 0; mi < 2; mi++) {
#pragma unroll
                    for (int s = 0; s < 2; s++) {
                        float* a = acc[mi][ni * 2 + s];
                        mma16816(a, ah[mi], bh[s], bh[s + 2]);
                        mma16816(a, ah[mi], bl[s], bl[s + 2]);
                        mma16816(a, al[mi], bh[s], bh[s + 2]);
                    }
                }
            }
        }
        __syncthreads();   // everyone done reading B[c]

        // load next B (bubble covered by co-resident block)
        if (c + 1 < NCHUNK) {
            const int k0 = (c + 1) * 64;
            load_tile64(sbase + GB_OFF,         bgh + k0, tid);
            load_tile64(sbase + GB_OFF + HTILE, bgl + k0, tid);
            CP_COMMIT();
        }
    }

    // ---- epilogue ----
    if (SPLIT) {
        __nv_bfloat16* H = (z == 0) ? H0 : (z == 1) ? H1 : H2;
        __nv_bfloat16* L = (z == 0) ? L0 : (z == 1) ? L1 : L2;
        const float sc = (z == 0) ? QSCALE : 1.0f;
#pragma unroll
        for (int mi = 0; mi < 2; mi++) {
            const int r0 = rowBase + wm + mi * 16 + (lane >> 2);
#pragma unroll
            for (int nj = 0; nj < 8; nj++) {
                const int col = colBase + wn + nj * 8 + (lane & 3) * 2;
                uint32_t h0, l0, h1, l1;
                split2(acc[mi][nj][0] * sc, acc[mi][nj][1] * sc, h0, l0);
                split2(acc[mi][nj][2] * sc, acc[mi][nj][3] * sc, h1, l1);
                *(uint32_t*)(H + (size_t)r0 * DM + col) = h0;
                *(uint32_t*)(L + (size_t)r0 * DM + col) = l0;
                *(uint32_t*)(H + (size_t)(r0 + 8) * DM + col) = h1;
                *(uint32_t*)(L + (size_t)(r0 + 8) * DM + col) = l1;
            }
        }
    } else {
#pragma unroll
        for (int mi = 0; mi < 2; mi++) {
            const int r0 = rowBase + wm + mi * 16 + (lane >> 2);
#pragma unroll
            for (int nj = 0; nj < 8; nj++) {
                const int col = colBase + wn + nj * 8 + (lane & 3) * 2;
                float2 bb = *(const float2*)(bias + col);
                float2 v0 = make_float2(acc[mi][nj][0] + bb.x, acc[mi][nj][1] + bb.y);
                float2 v1 = make_float2(acc[mi][nj][2] + bb.x, acc[mi][nj][3] + bb.y);
                *(float2*)(Cf + (size_t)r0 * DM + col) = v0;
                *(float2*)(Cf + (size_t)(r0 + 8) * DM + col) = v1;
            }
        }
    }
}

// ---------------- HMMA causal flash attention (R6 config: Q in regs) ----------------
// Block: 256 thr (8 warps), 128 queries x 64-key tiles, one (b,h) per block.y.
// S = QhKh + QhKl + QlKh; softmax via FFMA exp2 poly; O += PhVh + PhVl + PlVh.
// SMEM: 2 stages x (Kh|Kl|Vh|Vl, each 64x64 bf16 SW128) = 64KB.
#define AT_STAGE 32768
#define AT_SMEM  (2 * AT_STAGE)

__device__ __forceinline__ void load_kv_tiles(
    uint32_t sdst, const __nv_bfloat16* kh, const __nv_bfloat16* kl,
    const __nv_bfloat16* vh, const __nv_bfloat16* vl, int tid)
{
#pragma unroll
    for (int i = 0; i < 2; i++) {
        int f = i * 256 + tid;
        int r = f >> 3;
        int q = f & 7;
        uint32_t byte = (uint32_t)(r * 128 + q * 16);
        byte ^= ((byte >> 3) & 0x70);
        size_t go = (size_t)r * DM + q * 8;
        CP16(sdst + byte,         kh + go);
        CP16(sdst + 8192 + byte,  kl + go);
        CP16(sdst + 16384 + byte, vh + go);
        CP16(sdst + 24576 + byte, vl + go);
    }
}

__global__ __launch_bounds__(256, 1) void attn_mma_kernel(
    const __nv_bfloat16* __restrict__ Qh, const __nv_bfloat16* __restrict__ Ql,
    const __nv_bfloat16* __restrict__ Kh, const __nv_bfloat16* __restrict__ Kl,
    const __nv_bfloat16* __restrict__ Vh, const __nv_bfloat16* __restrict__ Vl,
    __nv_bfloat16* __restrict__ Ch, __nv_bfloat16* __restrict__ Cl)
{
    extern __shared__ __align__(1024) char sm[];
    const uint32_t sb = smem_u32(sm);
    const int tid = threadIdx.x;
    const int wid = tid >> 5;
    const int lane = tid & 31;
    const int mblk = (int)gridDim.x - 1 - (int)blockIdx.x;  // heavy-first
    const int bh = blockIdx.y;
    const int b = bh >> 4;
    const int h = bh & 15;
    const size_t headoff = (size_t)(b * Sq) * DM + h * HDv;
    const int wrow = wid * 16;
    const int lrow = lane & 15;
    const int lq = (lane >> 4) * 16;

    // hoisted swizzled address pieces
    const uint32_t swz = (uint32_t)((lrow & 7) << 4);
    uint32_t koff[4], rowb[4];
#pragma unroll
    for (int j = 0; j < 4; j++) {
        koff[j] = ((uint32_t)(j * 32 + lq)) ^ swz;
        rowb[j] = (uint32_t)((j * 16 + lrow) * 128);
    }

    // ---- prologue: stage Q tile (128x64 hi+lo), ldmatrix into regs ----
    const __nv_bfloat16* qgh = Qh + headoff + (size_t)(mblk * 128) * DM;
    const __nv_bfloat16* qgl = Ql + headoff + (size_t)(mblk * 128) * DM;
#pragma unroll
    for (int i = 0; i < 4; i++) {
        int f = i * 256 + tid;
        int r = f >> 3;
        int q = f & 7;
        uint32_t byte = (uint32_t)(r * 128 + q * 16);
        byte ^= ((byte >> 3) & 0x70);
        size_t go = (size_t)r * DM + q * 8;
        CP16(sb + byte, qgh + go);
        CP16(sb + 16384 + byte, qgl + go);
    }
    CP_COMMIT();
    CP_WAIT0();
    __syncthreads();

    uint32_t qfh[4][4], qfl[4][4];
    const uint32_t qrow = (uint32_t)((wrow + lrow) * 128);
#pragma unroll
    for (int ks = 0; ks < 4; ks++) {
        ldsm4(qfh[ks], sb + qrow + koff[ks]);
        ldsm4(qfl[ks], sb + 16384 + qrow + koff[ks]);
    }
    __syncthreads();

    // ---- tile 0 KV loads ----
    const __nv_bfloat16* kgh = Kh + headoff;
    const __nv_bfloat16* kgl = Kl + headoff;
    const __nv_bfloat16* vgh = Vh + headoff;
    const __nv_bfloat16* vgl = Vl + headoff;
    load_kv_tiles(sb, kgh, kgl, vgh, vgl, tid);
    CP_COMMIT();

    float Oacc[8][4];
#pragma unroll
    for (int nj = 0; nj < 8; nj++)
#pragma unroll
        for (int r = 0; r < 4; r++) Oacc[nj][r] = 0.f;
    float m0 = -INFINITY, m1 = -INFINITY, l0 = 0.f, l1 = 0.f;

    const int ntiles = 2 * mblk + 2;

    for (int t = 0; t < ntiles; t++) {
        CP_WAIT0();
        __syncthreads();
        const uint32_t cur = sb + (uint32_t)(t & 1) * AT_STAGE;

        if (t + 1 < ntiles) {
            const size_t off = (size_t)((t + 1) * 64) * DM;
            load_kv_tiles(sb + (uint32_t)((t + 1) & 1) * AT_STAGE,
                          kgh + off, kgl + off, vgh + off, vgl + off, tid);
            CP_COMMIT();
        }

        // ---- S = Q K^T (3 split terms) ----
        float S[8][4];
#pragma unroll
        for (int nj = 0; nj < 8; nj++)
#pragma unroll
            for (int r = 0; r < 4; r++) S[nj][r] = 0.f;

#pragma unroll
        for (int ks = 0; ks < 4; ks++) {
            const uint32_t ko = koff[ks];
            uint32_t kf_h[4][4], kf_l[4][4];
#pragma unroll
            for (int ni = 0; ni < 4; ni++) {
                ldsm4(kf_h[ni], cur + rowb[ni] + ko);
                ldsm4(kf_l[ni], cur + 8192 + rowb[ni] + ko);
            }
#pragma unroll
            for (int nj = 0; nj < 8; nj++) {
                const int ni = nj >> 1, s = nj & 1;
                mma16816(S[nj], qfh[ks], kf_h[ni][s], kf_h[ni][s + 2]);
                mma16816(S[nj], qfh[ks], kf_l[ni][s], kf_l[ni][s + 2]);
                mma16816(S[nj], qfl[ks], kf_h[ni][s], kf_h[ni][s + 2]);
            }
        }

        // ---- causal mask (last two tiles only) ----
        if (t >= ntiles - 2) {
            const int rg0 = mblk * 128 + wrow + (lane >> 2);
            const int rg1 = rg0 + 8;
            const int cb = t * 64 + (lane & 3) * 2;
#pragma unroll
            for (int nj = 0; nj < 8; nj++) {
                const int c0 = cb + nj * 8, c1 = c0 + 1;
                if (c0 > rg0) S[nj][0] = -1e30f;
                if (c1 > rg0) S[nj][1] = -1e30f;
                if (c0 > rg1) S[nj][2] = -1e30f;
                if (c1 > rg1) S[nj][3] = -1e30f;
            }
        }

        // ---- online softmax (exp2 poly on FFMA pipe) ----
        float mt0 = -INFINITY, mt1 = -INFINITY;
#pragma unroll
        for (int nj = 0; nj < 8; nj++) {
            mt0 = fmaxf(mt0, fmaxf(S[nj][0], S[nj][1]));
            mt1 = fmaxf(mt1, fmaxf(S[nj][2], S[nj][3]));
        }
        mt0 = fmaxf(mt0, __shfl_xor_sync(0xffffffffu, mt0, 1));
        mt0 = fmaxf(mt0, __shfl_xor_sync(0xffffffffu, mt0, 2));
        mt1 = fmaxf(mt1, __shfl_xor_sync(0xffffffffu, mt1, 1));
        mt1 = fmaxf(mt1, __shfl_xor_sync(0xffffffffu, mt1, 2));
        const float mn0 = fmaxf(m0, mt0), mn1 = fmaxf(m1, mt1);
        const float a0 = exp2p(m0 - mn0), a1 = exp2p(m1 - mn1);
        m0 = mn0; m1 = mn1;
        l0 *= a0; l1 *= a1;
        float rs0 = 0.f, rs1 = 0.f;
#pragma unroll
        for (int nj = 0; nj < 8; nj++) {
            Oacc[nj][0] *= a0; Oacc[nj][1] *= a0;
            Oacc[nj][2] *= a1; Oacc[nj][3] *= a1;
            S[nj][0] = exp2p(S[nj][0] - mn0);
            S[nj][1] = exp2p(S[nj][1] - mn0);
            S[nj][2] = exp2p(S[nj][2] - mn1);
            S[nj][3] = exp2p(S[nj][3] - mn1);
            rs0 += S[nj][0] + S[nj][1];
            rs1 += S[nj][2] + S[nj][3];
        }
        l0 += rs0; l1 += rs1;

        // ---- O += P V (3 split terms; V^T via ldmatrix.trans) ----
#pragma unroll
        for (int kk = 0; kk < 4; kk++) {
            uint32_t pah[4], pal[4];
            split2(S[2 * kk][0],     S[2 * kk][1],     pah[0], pal[0]);
            split2(S[2 * kk][2],     S[2 * kk][3],     pah[1], pal[1]);
            split2(S[2 * kk + 1][0], S[2 * kk + 1][1], pah[2], pal[2]);
            split2(S[2 * kk + 1][2], S[2 * kk + 1][3], pah[3], pal[3]);
#pragma unroll
            for (int dp = 0; dp < 4; dp++) {
                const uint32_t vb = cur + rowb[kk] + koff[dp];
                uint32_t vfh[4], vfl[4];
                ldsm4t(vfh, vb + 16384);
                ldsm4t(vfl, vb + 24576);
                mma16816(Oacc[2 * dp], pah, vfh[0], vfh[1]);
                mma16816(Oacc[2 * dp], pah, vfl[0], vfl[1]);
                mma16816(Oacc[2 * dp], pal, vfh[0], vfh[1]);
                mma16816(Oacc[2 * dp + 1], pah, vfh[2], vfh[3]);
                mma16816(Oacc[2 * dp + 1], pah, vfl[2], vfl[3]);
                mma16816(Oacc[2 * dp + 1], pal, vfh[2], vfh[3]);
            }
        }
    }

    // ---- epilogue ----
    l0 += __shfl_xor_sync(0xffffffffu, l0, 1);
    l0 += __shfl_xor_sync(0xffffffffu, l0, 2);
    l1 += __shfl_xor_sync(0xffffffffu, l1, 1);
    l1 += __shfl_xor_sync(0xffffffffu, l1, 2);
    const float inv0 = 1.f / l0, inv1 = 1.f / l1;
    const size_t tok0 = (size_t)(b * Sq + mblk * 128 + wrow + (lane >> 2));
    const size_t tok1 = tok0 + 8;
    const int colb = h * HDv + (lane & 3) * 2;
#pragma unroll
    for (int nj = 0; nj < 8; nj++) {
        const int col = colb + nj * 8;
        uint32_t h0, lo0, h1, lo1;
        split2(Oacc[nj][0] * inv0, Oacc[nj][1] * inv0, h0, lo0);
        split2(Oacc[nj][2] * inv1, Oacc[nj][3] * inv1, h1, lo1);
        *(uint32_t*)(Ch + tok0 * DM + col) = h0;
        *(uint32_t*)(Cl + tok0 * DM + col) = lo0;
        *(uint32_t*)(Ch + tok1 * DM + col) = h1;
        *(uint32_t*)(Cl + tok1 * DM + col) = lo1;
    }
}

// ---------------------------------------------------------------------------
extern "C" void kernel_launch(void* const* d_in, const int* in_sizes, int n_in,
                              void* d_out, int out_size)
{
    const float* x  = (const float*)d_in[0];
    const float* Wq = (const float*)d_in[1];
    const float* Wk = (const float*)d_in[2];
    const float* Wv = (const float*)d_in[3];
    const float* Wo = (const float*)d_in[4];
    const float* bo = (const float*)d_in[5];
    float* out = (float*)d_out;

    __nv_bfloat16 *xh, *xl, *qh, *ql, *kh, *kl, *vh, *vl, *ch, *cl, *wth, *wtl;
    cudaGetSymbolAddress((void**)&xh, g_xh);
    cudaGetSymbolAddress((void**)&xl, g_xl);
    cudaGetSymbolAddress((void**)&qh, g_qh);
    cudaGetSymbolAddress((void**)&ql, g_ql);
    cudaGetSymbolAddress((void**)&kh, g_kh);
    cudaGetSymbolAddress((void**)&kl, g_kl);
    cudaGetSymbolAddress((void**)&vh, g_vh);
    cudaGetSymbolAddress((void**)&vl, g_vl);
    cudaGetSymbolAddress((void**)&ch, g_ch);
    cudaGetSymbolAddress((void**)&cl, g_cl);
    cudaGetSymbolAddress((void**)&wth, g_wth);
    cudaGetSymbolAddress((void**)&wtl, g_wtl);

    static int attr_set = 0;
    if (!attr_set) {
        cudaFuncSetAttribute(gemm_hmma_kernel<true>,
                             cudaFuncAttributeMaxDynamicSharedMemorySize, GEMM_SMEM);
        cudaFuncSetAttribute(gemm_hmma_kernel<false>,
                             cudaFuncAttributeMaxDynamicSharedMemorySize, GEMM_SMEM);
        cudaFuncSetAttribute(attn_mma_kernel,
                             cudaFuncAttributeMaxDynamicSharedMemorySize, AT_SMEM);
        attr_set = 1;
    }

    const int n4 = Mrows * DM / 4;
    fsplit_kernel<<<(n4 + 255) / 256, 256>>>(x, xh, xl, n4);
    wsplit_kernel<<<dim3(32, 32, 4), 256>>>(Wq, Wk, Wv, Wo, wth, wtl);

    // QKV projections -> split bf16 outputs (Q pre-scaled by 0.125*log2e)
    gemm_hmma_kernel<true><<<dim3(DM / 128, Mrows / 128, 3), 256, GEMM_SMEM>>>(
        xh, xl, wth, wtl, qh, ql, kh, kl, vh, vl, nullptr, nullptr);

    attn_mma_kernel<<<dim3(Sq / 128, Bsz * Hh), 256, AT_SMEM>>>(
        qh, ql, kh, kl, vh, vl, ch, cl);

    // output projection (+bias)
    gemm_hmma_kernel<false><<<dim3(DM / 128, Mrows / 128, 1), 256, GEMM_SMEM>>>(
        ch, cl, wth + (size_t)3 * DM * DM, wtl + (size_t)3 * DM * DM,
        nullptr, nullptr, nullptr, nullptr, nullptr, nullptr, out, bo);
}

// round 9
// speedup vs baseline: 1.0431x; 1.0005x over previous
#include <cuda_runtime.h>
#include <cuda_bf16.h>
#include <math.h>
#include <stdint.h>

#define Bsz 2
#define Sq 2048
#define DM 1024
#define Hh 16
#define HDv 64
#define Mrows (Bsz*Sq)   /* 4096 */

#define QSCALE 0.18033688011112042f   /* 0.125 * log2(e) */

// ---------------- scratch (device globals; no allocs allowed) ----------------
__device__ __nv_bfloat16 g_xh[Mrows*DM];
__device__ __nv_bfloat16 g_xl[Mrows*DM];
__device__ __nv_bfloat16 g_qh[Mrows*DM];
__device__ __nv_bfloat16 g_ql[Mrows*DM];
__device__ __nv_bfloat16 g_kh[Mrows*DM];
__device__ __nv_bfloat16 g_kl[Mrows*DM];
__device__ __nv_bfloat16 g_vh[Mrows*DM];
__device__ __nv_bfloat16 g_vl[Mrows*DM];
__device__ __nv_bfloat16 g_ch[Mrows*DM];
__device__ __nv_bfloat16 g_cl[Mrows*DM];
__device__ __nv_bfloat16 g_wth[4*DM*DM];   // W^T split-hi, [N][K], order q,k,v,o
__device__ __nv_bfloat16 g_wtl[4*DM*DM];   // W^T split-lo

// ---------------- helpers ----------------
__device__ __forceinline__ uint32_t smem_u32(const void* p) {
    uint32_t a;
    asm("{ .reg .u64 t; cvta.to.shared.u64 t, %1; cvt.u32.u64 %0, t; }" : "=r"(a) : "l"(p));
    return a;
}
__device__ __forceinline__ void ldsm4(uint32_t* r, uint32_t addr) {
    asm volatile("ldmatrix.sync.aligned.m8n8.x4.shared.b16 {%0,%1,%2,%3}, [%4];"
                 : "=r"(r[0]), "=r"(r[1]), "=r"(r[2]), "=r"(r[3]) : "r"(addr));
}
__device__ __forceinline__ void ldsm4t(uint32_t* r, uint32_t addr) {
    asm volatile("ldmatrix.sync.aligned.m8n8.x4.trans.shared.b16 {%0,%1,%2,%3}, [%4];"
                 : "=r"(r[0]), "=r"(r[1]), "=r"(r[2]), "=r"(r[3]) : "r"(addr));
}
__device__ __forceinline__ void mma16816(float* c, const uint32_t* a, uint32_t b0, uint32_t b1) {
    asm volatile("mma.sync.aligned.m16n8k16.row.col.f32.bf16.bf16.f32 "
                 "{%0,%1,%2,%3}, {%4,%5,%6,%7}, {%8,%9}, {%0,%1,%2,%3};"
                 : "+f"(c[0]), "+f"(c[1]), "+f"(c[2]), "+f"(c[3])
                 : "r"(a[0]), "r"(a[1]), "r"(a[2]), "r"(a[3]), "r"(b0), "r"(b1));
}
#define CP_COMMIT() asm volatile("cp.async.commit_group;" ::: "memory")
#define CP_WAIT0()  asm volatile("cp.async.wait_group 0;" ::: "memory")
#define CP16(dst, src) asm volatile("cp.async.cg.shared.global [%0], [%1], 16;" :: "r"(dst), "l"(src) : "memory")

__device__ __forceinline__ uint32_t packbf2(float x, float y) {
    __nv_bfloat162 t = __floats2bfloat162_rn(x, y);
    return *(uint32_t*)&t;
}
// split a pair of floats into bf16 hi + bf16 lo packed regs
__device__ __forceinline__ void split2(float x, float y, uint32_t& h, uint32_t& l) {
    __nv_bfloat16 hx = __float2bfloat16(x), hy = __float2bfloat16(y);
    __nv_bfloat162 hh; hh.x = hx; hh.y = hy;
    h = *(uint32_t*)&hh;
    l = packbf2(x - __bfloat162float(hx), y - __bfloat162float(hy));
}
// fast exp2 for x <= 0: magic round + degree-5 Taylor (err ~3e-6); FFMA pipe only
__device__ __forceinline__ float exp2p(float x) {
    x = fmaxf(x, -60.0f);
    float r = x + 12582912.0f;
    int n = __float_as_int(r) - 0x4B400000;
    float f = x - (r - 12582912.0f);
    float p = 1.3333558e-3f;
    p = fmaf(p, f, 9.6181291e-3f);
    p = fmaf(p, f, 5.5504109e-2f);
    p = fmaf(p, f, 2.4022651e-1f);
    p = fmaf(p, f, 6.9314718e-1f);
    p = fmaf(p, f, 1.0f);
    return __int_as_float(__float_as_int(p) + (n << 23));
}

// ---------------- fp32 -> bf16 hi/lo split (elementwise) ----------------
__global__ __launch_bounds__(256) void fsplit_kernel(
    const float* __restrict__ src, __nv_bfloat16* __restrict__ h,
    __nv_bfloat16* __restrict__ l, int n4)
{
    int idx = blockIdx.x * 256 + threadIdx.x;
    if (idx >= n4) return;
    float4 v = ((const float4*)src)[idx];
    uint32_t h0, l0, h1, l1;
    split2(v.x, v.y, h0, l0);
    split2(v.z, v.w, h1, l1);
    ((uint32_t*)h)[idx * 2 + 0] = h0;
    ((uint32_t*)h)[idx * 2 + 1] = h1;
    ((uint32_t*)l)[idx * 2 + 0] = l0;
    ((uint32_t*)l)[idx * 2 + 1] = l1;
}

// ---------------- W[K][N] fp32 -> W^T[N][K] bf16 hi/lo ----------------
__global__ __launch_bounds__(256) void wsplit_kernel(
    const float* __restrict__ W0, const float* __restrict__ W1,
    const float* __restrict__ W2, const float* __restrict__ W3,
    __nv_bfloat16* __restrict__ oh, __nv_bfloat16* __restrict__ ol)
{
    __shared__ float t[32][33];
    int z = blockIdx.z;
    const float* W = (z == 0) ? W0 : (z == 1) ? W1 : (z == 2) ? W2 : W3;
    size_t zoff = (size_t)z * DM * DM;
    int bn = blockIdx.x * 32;
    int bk = blockIdx.y * 32;
    int tx = threadIdx.x & 31;
    int ty = threadIdx.x >> 5;
#pragma unroll
    for (int r = 0; r < 4; r++)
        t[ty + 8 * r][tx] = W[(size_t)(bk + ty + 8 * r) * DM + bn + tx];
    __syncthreads();
#pragma unroll
    for (int r = 0; r < 4; r++) {
        int nl = ty + 8 * r;
        float v = t[tx][nl];
        __nv_bfloat16 h = __float2bfloat16(v);
        __nv_bfloat16 l = __float2bfloat16(v - __bfloat162float(h));
        oh[zoff + (size_t)(bn + nl) * DM + bk + tx] = h;
        ol[zoff + (size_t)(bn + nl) * DM + bk + tx] = l;
    }
}

// ---------------- HMMA bf16-split GEMM (R7/R8 config: 2 blocks/SM) ----------------
#define HTILE 16384                    /* 128 rows x 64 bf16 */
#define GA_STAGE (2 * HTILE)           /* Ah + Al per stage = 32KB */
#define GB_OFF   (2 * GA_STAGE)        /* B area at 64KB */
#define GEMM_SMEM (GB_OFF + 2 * HTILE) /* 96KB */

__device__ __forceinline__ void load_tile64(uint32_t sdst, const __nv_bfloat16* g, int tid) {
#pragma unroll
    for (int i = 0; i < 4; i++) {
        int f = i * 256 + tid;
        int r = f >> 3;
        int q = f & 7;
        uint32_t byte = (uint32_t)(r * 128 + q * 16);
        byte ^= ((byte >> 3) & 0x70);
        CP16(sdst + byte, g + (size_t)r * DM + q * 8);
    }
}

template<bool SPLIT>
__global__ __launch_bounds__(256, 2) void gemm_hmma_kernel(
    const __nv_bfloat16* __restrict__ Ah, const __nv_bfloat16* __restrict__ Al,
    const __nv_bfloat16* __restrict__ Bh_base, const __nv_bfloat16* __restrict__ Bl_base,
    __nv_bfloat16* H0, __nv_bfloat16* L0,
    __nv_bfloat16* H1, __nv_bfloat16* L1,
    __nv_bfloat16* H2, __nv_bfloat16* L2,
    float* __restrict__ Cf, const float* __restrict__ bias)
{
    extern __shared__ __align__(1024) char sm[];
    const int tid = threadIdx.x;
    const int wid = tid >> 5;
    const int lane = tid & 31;
    const int z = blockIdx.z;
    const int colBase = blockIdx.x * 128;
    const int rowBase = blockIdx.y * 128;
    const int wm = (wid & 3) * 32;
    const int wn = (wid >> 2) * 64;

    const uint32_t sbase = smem_u32(sm);
    const __nv_bfloat16* agh = Ah + (size_t)rowBase * DM;
    const __nv_bfloat16* agl = Al + (size_t)rowBase * DM;
    const __nv_bfloat16* bgh = Bh_base + (size_t)z * DM * DM + (size_t)colBase * DM;
    const __nv_bfloat16* bgl = Bl_base + (size_t)z * DM * DM + (size_t)colBase * DM;

    float acc[2][8][4];
#pragma unroll
    for (int mi = 0; mi < 2; mi++)
#pragma unroll
        for (int nj = 0; nj < 8; nj++)
#pragma unroll
            for (int r = 0; r < 4; r++) acc[mi][nj][r] = 0.f;

    const int lrow = lane & 15;
    const int lquad = (lane >> 4) << 4;
    const uint32_t swz = (uint32_t)((lrow & 7) << 4);
    uint32_t koff[4], arow[2], brow[4];
#pragma unroll
    for (int ks = 0; ks < 4; ks++) koff[ks] = ((uint32_t)(ks * 32 + lquad)) ^ swz;
#pragma unroll
    for (int i = 0; i < 2; i++) arow[i] = (uint32_t)((wm + i * 16 + lrow) * 128);
#pragma unroll
    for (int i = 0; i < 4; i++) brow[i] = (uint32_t)((wn + i * 16 + lrow) * 128);

    load_tile64(sbase,          agh, tid);
    load_tile64(sbase + HTILE,  agl, tid);
    load_tile64(sbase + GB_OFF,         bgh, tid);
    load_tile64(sbase + GB_OFF + HTILE, bgl, tid);
    CP_COMMIT();

    const int NCHUNK = DM / 64;  // 16

    for (int c = 0; c < NCHUNK; c++) {
        CP_WAIT0();
        __syncthreads();
        const uint32_t Ab = sbase + (uint32_t)(c & 1) * GA_STAGE;

        if (c + 1 < NCHUNK) {
            const uint32_t nst = sbase + (uint32_t)((c + 1) & 1) * GA_STAGE;
            const int k0 = (c + 1) * 64;
            load_tile64(nst,         agh + k0, tid);
            load_tile64(nst + HTILE, agl + k0, tid);
            CP_COMMIT();
        }

#pragma unroll
        for (int ks = 0; ks < 4; ks++) {
            const uint32_t ko = koff[ks];
            uint32_t ah[2][4], al[2][4];
#pragma unroll
            for (int mi = 0; mi < 2; mi++) {
                ldsm4(ah[mi], Ab + arow[mi] + ko);
                ldsm4(al[mi], Ab + HTILE + arow[mi] + ko);
            }
#pragma unroll
            for (int ni = 0; ni < 4; ni++) {
                uint32_t bh[4], bl[4];
                ldsm4(bh, sbase + GB_OFF + brow[ni] + ko);
                ldsm4(bl, sbase + GB_OFF + HTILE + brow[ni] + ko);
#pragma unroll
                for (int mi = 0; mi < 2; mi++) {
#pragma unroll
                    for (int s = 0; s < 2; s++) {
                        float* a = acc[mi][ni * 2 + s];
                        mma16816(a, ah[mi], bh[s], bh[s + 2]);
                        mma16816(a, ah[mi], bl[s], bl[s + 2]);
                        mma16816(a, al[mi], bh[s], bh[s + 2]);
                    }
                }
            }
        }
        __syncthreads();

        if (c + 1 < NCHUNK) {
            const int k0 = (c + 1) * 64;
            load_tile64(sbase + GB_OFF,         bgh + k0, tid);
            load_tile64(sbase + GB_OFF + HTILE, bgl + k0, tid);
            CP_COMMIT();
        }
    }

    if (SPLIT) {
        __nv_bfloat16* H = (z == 0) ? H0 : (z == 1) ? H1 : H2;
        __nv_bfloat16* L = (z == 0) ? L0 : (z == 1) ? L1 : L2;
        const float sc = (z == 0) ? QSCALE : 1.0f;
#pragma unroll
        for (int mi = 0; mi < 2; mi++) {
            const int r0 = rowBase + wm + mi * 16 + (lane >> 2);
#pragma unroll
            for (int nj = 0; nj < 8; nj++) {
                const int col = colBase + wn + nj * 8 + (lane & 3) * 2;
                uint32_t h0, l0, h1, l1;
                split2(acc[mi][nj][0] * sc, acc[mi][nj][1] * sc, h0, l0);
                split2(acc[mi][nj][2] * sc, acc[mi][nj][3] * sc, h1, l1);
                *(uint32_t*)(H + (size_t)r0 * DM + col) = h0;
                *(uint32_t*)(L + (size_t)r0 * DM + col) = l0;
                *(uint32_t*)(H + (size_t)(r0 + 8) * DM + col) = h1;
                *(uint32_t*)(L + (size_t)(r0 + 8) * DM + col) = l1;
            }
        }
    } else {
#pragma unroll
        for (int mi = 0; mi < 2; mi++) {
            const int r0 = rowBase + wm + mi * 16 + (lane >> 2);
#pragma unroll
            for (int nj = 0; nj < 8; nj++) {
                const int col = colBase + wn + nj * 8 + (lane & 3) * 2;
                float2 bb = *(const float2*)(bias + col);
                float2 v0 = make_float2(acc[mi][nj][0] + bb.x, acc[mi][nj][1] + bb.y);
                float2 v1 = make_float2(acc[mi][nj][2] + bb.x, acc[mi][nj][3] + bb.y);
                *(float2*)(Cf + (size_t)r0 * DM + col) = v0;
                *(float2*)(Cf + (size_t)(r0 + 8) * DM + col) = v1;
            }
        }
    }
}

// ---------------- HMMA causal flash attention, lag-1 PV pipeline ----------------
// Block: 256 thr (8 warps), 128 queries x 64-key tiles, one (b,h) per block.y.
// Iter t: S(t) MMAs -> max reduce -> [PV(t-1) MMAs interleaved with exp2/split
// of P(t) so FFMAs issue in HMMA shadows] -> Oacc *= alpha(t). Final PV in
// epilogue. 3-stage KV ring (96KB) keeps V(t-1) live during prefetch of t+1.
#define AT_STAGE 32768
#define AT_SMEM  (3 * AT_STAGE)

__device__ __forceinline__ void load_kv_tiles(
    uint32_t sdst, const __nv_bfloat16* kh, const __nv_bfloat16* kl,
    const __nv_bfloat16* vh, const __nv_bfloat16* vl, int tid)
{
#pragma unroll
    for (int i = 0; i < 2; i++) {
        int f = i * 256 + tid;
        int r = f >> 3;
        int q = f & 7;
        uint32_t byte = (uint32_t)(r * 128 + q * 16);
        byte ^= ((byte >> 3) & 0x70);
        size_t go = (size_t)r * DM + q * 8;
        CP16(sdst + byte,         kh + go);
        CP16(sdst + 8192 + byte,  kl + go);
        CP16(sdst + 16384 + byte, vh + go);
        CP16(sdst + 24576 + byte, vl + go);
    }
}

__global__ __launch_bounds__(256, 1) void attn_mma_kernel(
    const __nv_bfloat16* __restrict__ Qh, const __nv_bfloat16* __restrict__ Ql,
    const __nv_bfloat16* __restrict__ Kh, const __nv_bfloat16* __restrict__ Kl,
    const __nv_bfloat16* __restrict__ Vh, const __nv_bfloat16* __restrict__ Vl,
    __nv_bfloat16* __restrict__ Ch, __nv_bfloat16* __restrict__ Cl)
{
    extern __shared__ __align__(1024) char sm[];
    const uint32_t sb = smem_u32(sm);
    const int tid = threadIdx.x;
    const int wid = tid >> 5;
    const int lane = tid & 31;
    const int mblk = (int)gridDim.x - 1 - (int)blockIdx.x;  // heavy-first
    const int bh = blockIdx.y;
    const int b = bh >> 4;
    const int h = bh & 15;
    const size_t headoff = (size_t)(b * Sq) * DM + h * HDv;
    const int wrow = wid * 16;
    const int lrow = lane & 15;
    const int lq = (lane >> 4) * 16;

    const uint32_t swz = (uint32_t)((lrow & 7) << 4);
    uint32_t koff[4], rowb[4];
#pragma unroll
    for (int j = 0; j < 4; j++) {
        koff[j] = ((uint32_t)(j * 32 + lq)) ^ swz;
        rowb[j] = (uint32_t)((j * 16 + lrow) * 128);
    }

    // ---- prologue: stage Q tile (128x64 hi+lo) in stage-0 area, ldmatrix to regs ----
    const __nv_bfloat16* qgh = Qh + headoff + (size_t)(mblk * 128) * DM;
    const __nv_bfloat16* qgl = Ql + headoff + (size_t)(mblk * 128) * DM;
#pragma unroll
    for (int i = 0; i < 4; i++) {
        int f = i * 256 + tid;
        int r = f >> 3;
        int q = f & 7;
        uint32_t byte = (uint32_t)(r * 128 + q * 16);
        byte ^= ((byte >> 3) & 0x70);
        size_t go = (size_t)r * DM + q * 8;
        CP16(sb + byte, qgh + go);
        CP16(sb + 16384 + byte, qgl + go);
    }
    CP_COMMIT();
    CP_WAIT0();
    __syncthreads();

    uint32_t qfh[4][4], qfl[4][4];
    const uint32_t qrow = (uint32_t)((wrow + lrow) * 128);
#pragma unroll
    for (int ks = 0; ks < 4; ks++) {
        ldsm4(qfh[ks], sb + qrow + koff[ks]);
        ldsm4(qfl[ks], sb + 16384 + qrow + koff[ks]);
    }
    __syncthreads();

    // ---- KV tile 0 into ring stage 0 ----
    const __nv_bfloat16* kgh = Kh + headoff;
    const __nv_bfloat16* kgl = Kl + headoff;
    const __nv_bfloat16* vgh = Vh + headoff;
    const __nv_bfloat16* vgl = Vl + headoff;
    load_kv_tiles(sb, kgh, kgl, vgh, vgl, tid);
    CP_COMMIT();

    float Oacc[8][4];
#pragma unroll
    for (int nj = 0; nj < 8; nj++)
#pragma unroll
        for (int r = 0; r < 4; r++) Oacc[nj][r] = 0.f;
    float m0 = -INFINITY, m1 = -INFINITY, l0 = 0.f, l1 = 0.f;
    uint32_t pah[4][4], pal[4][4];   // P(t-1) fragments, persist across iters

    const int ntiles = 2 * mblk + 2;
    int st = 0;           // ring slot of tile t
    int stp = 2;          // ring slot of tile t-1

    for (int t = 0; t < ntiles; t++) {
        CP_WAIT0();
        __syncthreads();
        const uint32_t cur = sb + (uint32_t)st * AT_STAGE;
        const uint32_t prev = sb + (uint32_t)stp * AT_STAGE;

        if (t + 1 < ntiles) {
            const size_t off = (size_t)((t + 1) * 64) * DM;
            int sn = (st + 1 == 3) ? 0 : st + 1;
            load_kv_tiles(sb + (uint32_t)sn * AT_STAGE,
                          kgh + off, kgl + off, vgh + off, vgl + off, tid);
            CP_COMMIT();
        }

        // ---- S = Q K^T (3 split terms) ----
        float S[8][4];
#pragma unroll
        for (int nj = 0; nj < 8; nj++)
#pragma unroll
            for (int r = 0; r < 4; r++) S[nj][r] = 0.f;

#pragma unroll
        for (int ks = 0; ks < 4; ks++) {
            const uint32_t ko = koff[ks];
            uint32_t kf_h[4][4], kf_l[4][4];
#pragma unroll
            for (int ni = 0; ni < 4; ni++) {
                ldsm4(kf_h[ni], cur + rowb[ni] + ko);
                ldsm4(kf_l[ni], cur + 8192 + rowb[ni] + ko);
            }
#pragma unroll
            for (int nj = 0; nj < 8; nj++) {
                const int ni = nj >> 1, s = nj & 1;
                mma16816(S[nj], qfh[ks], kf_h[ni][s], kf_h[ni][s + 2]);
                mma16816(S[nj], qfh[ks], kf_l[ni][s], kf_l[ni][s + 2]);
                mma16816(S[nj], qfl[ks], kf_h[ni][s], kf_h[ni][s + 2]);
            }
        }

        // ---- causal mask (last two tiles only) ----
        if (t >= ntiles - 2) {
            const int rg0 = mblk * 128 + wrow + (lane >> 2);
            const int rg1 = rg0 + 8;
            const int cb = t * 64 + (lane & 3) * 2;
#pragma unroll
            for (int nj = 0; nj < 8; nj++) {
                const int c0 = cb + nj * 8, c1 = c0 + 1;
                if (c0 > rg0) S[nj][0] = -1e30f;
                if (c1 > rg0) S[nj][1] = -1e30f;
                if (c0 > rg1) S[nj][2] = -1e30f;
                if (c1 > rg1) S[nj][3] = -1e30f;
            }
        }

        // ---- max reduce ----
        float mt0 = -INFINITY, mt1 = -INFINITY;
#pragma unroll
        for (int nj = 0; nj < 8; nj++) {
            mt0 = fmaxf(mt0, fmaxf(S[nj][0], S[nj][1]));
            mt1 = fmaxf(mt1, fmaxf(S[nj][2], S[nj][3]));
        }
        mt0 = fmaxf(mt0, __shfl_xor_sync(0xffffffffu, mt0, 1));
        mt0 = fmaxf(mt0, __shfl_xor_sync(0xffffffffu, mt0, 2));
        mt1 = fmaxf(mt1, __shfl_xor_sync(0xffffffffu, mt1, 1));
        mt1 = fmaxf(mt1, __shfl_xor_sync(0xffffffffu, mt1, 2));
        const float mn0 = fmaxf(m0, mt0), mn1 = fmaxf(m1, mt1);
        const float a0 = exp2p(m0 - mn0), a1 = exp2p(m1 - mn1);
        m0 = mn0; m1 = mn1;

        float rs0 = 0.f, rs1 = 0.f;

        if (t > 0) {
            // ---- PV(t-1) MMAs interleaved with exp2/split of P(t) ----
#pragma unroll
            for (int kk = 0; kk < 4; kk++) {
#pragma unroll
                for (int dp = 0; dp < 4; dp++) {
                    const uint32_t vb = prev + rowb[kk] + koff[dp];
                    uint32_t vfh[4], vfl[4];
                    ldsm4t(vfh, vb + 16384);
                    ldsm4t(vfl, vb + 24576);
                    mma16816(Oacc[2 * dp],     pah[kk], vfh[0], vfh[1]);
                    mma16816(Oacc[2 * dp],     pah[kk], vfl[0], vfl[1]);
                    mma16816(Oacc[2 * dp],     pal[kk], vfh[0], vfh[1]);
                    mma16816(Oacc[2 * dp + 1], pah[kk], vfh[2], vfh[3]);
                    mma16816(Oacc[2 * dp + 1], pah[kk], vfl[2], vfl[3]);
                    mma16816(Oacc[2 * dp + 1], pal[kk], vfh[2], vfh[3]);
                    // 2 exps of P(t) in the HMMA shadow
                    {
                        const int o0 = dp * 2, o1 = o0 + 1;
                        const int r0i = 2 * kk + (o0 >> 2), c0i = o0 & 3;
                        const int r1i = 2 * kk + (o1 >> 2), c1i = o1 & 3;
                        S[r0i][c0i] = exp2p(S[r0i][c0i] - ((c0i < 2) ? mn0 : mn1));
                        S[r1i][c1i] = exp2p(S[r1i][c1i] - ((c1i < 2) ? mn0 : mn1));
                    }
                }
                // split P(t) rows 2kk,2kk+1 (all 8 exps done); overwrites pah[kk]
                // AFTER all PV(t-1) MMAs reading it were issued above.
                rs0 += S[2 * kk][0] + S[2 * kk][1] + S[2 * kk + 1][0] + S[2 * kk + 1][1];
                rs1 += S[2 * kk][2] + S[2 * kk][3] + S[2 * kk + 1][2] + S[2 * kk + 1][3];
                split2(S[2 * kk][0],     S[2 * kk][1],     pah[kk][0], pal[kk][0]);
                split2(S[2 * kk][2],     S[2 * kk][3],     pah[kk][1], pal[kk][1]);
                split2(S[2 * kk + 1][0], S[2 * kk + 1][1], pah[kk][2], pal[kk][2]);
                split2(S[2 * kk + 1][2], S[2 * kk + 1][3], pah[kk][3], pal[kk][3]);
            }
        } else {
            // t == 0: no pending PV; plain exp + split
#pragma unroll
            for (int kk = 0; kk < 4; kk++) {
#pragma unroll
                for (int rr = 0; rr < 2; rr++) {
                    const int nj = 2 * kk + rr;
                    S[nj][0] = exp2p(S[nj][0] - mn0);
                    S[nj][1] = exp2p(S[nj][1] - mn0);
                    S[nj][2] = exp2p(S[nj][2] - mn1);
                    S[nj][3] = exp2p(S[nj][3] - mn1);
                    rs0 += S[nj][0] + S[nj][1];
                    rs1 += S[nj][2] + S[nj][3];
                }
                split2(S[2 * kk][0],     S[2 * kk][1],     pah[kk][0], pal[kk][0]);
                split2(S[2 * kk][2],     S[2 * kk][3],     pah[kk][1], pal[kk][1]);
                split2(S[2 * kk + 1][0], S[2 * kk + 1][1], pah[kk][2], pal[kk][2]);
                split2(S[2 * kk + 1][2], S[2 * kk + 1][3], pah[kk][3], pal[kk][3]);
            }
        }

        // ---- rescale O (after PV(t-1) was added) and l ----
        l0 = l0 * a0 + rs0;
        l1 = l1 * a1 + rs1;
#pragma unroll
        for (int nj = 0; nj < 8; nj++) {
            Oacc[nj][0] *= a0; Oacc[nj][1] *= a0;
            Oacc[nj][2] *= a1; Oacc[nj][3] *= a1;
        }

        stp = st;
        st = (st + 1 == 3) ? 0 : st + 1;
    }

    // ---- drain: final PV(ntiles-1) ----
    {
        const uint32_t prev = sb + (uint32_t)stp * AT_STAGE;
#pragma unroll
        for (int kk = 0; kk < 4; kk++) {
#pragma unroll
            for (int dp = 0; dp < 4; dp++) {
                const uint32_t vb = prev + rowb[kk] + koff[dp];
                uint32_t vfh[4], vfl[4];
                ldsm4t(vfh, vb + 16384);
                ldsm4t(vfl, vb + 24576);
                mma16816(Oacc[2 * dp],     pah[kk], vfh[0], vfh[1]);
                mma16816(Oacc[2 * dp],     pah[kk], vfl[0], vfl[1]);
                mma16816(Oacc[2 * dp],     pal[kk], vfh[0], vfh[1]);
                mma16816(Oacc[2 * dp + 1], pah[kk], vfh[2], vfh[3]);
                mma16816(Oacc[2 * dp + 1], pah[kk], vfl[2], vfl[3]);
                mma16816(Oacc[2 * dp + 1], pal[kk], vfh[2], vfh[3]);
            }
        }
    }

    // ---- epilogue: reduce l over quad, normalize, split-store ----
    l0 += __shfl_xor_sync(0xffffffffu, l0, 1);
    l0 += __shfl_xor_sync(0xffffffffu, l0, 2);
    l1 += __shfl_xor_sync(0xffffffffu, l1, 1);
    l1 += __shfl_xor_sync(0xffffffffu, l1, 2);
    const float inv0 = 1.f / l0, inv1 = 1.f / l1;
    const size_t tok0 = (size_t)(b * Sq + mblk * 128 + wrow + (lane >> 2));
    const size_t tok1 = tok0 + 8;
    const int colb = h * HDv + (lane & 3) * 2;
#pragma unroll
    for (int nj = 0; nj < 8; nj++) {
        const int col = colb + nj * 8;
        uint32_t h0, lo0, h1, lo1;
        split2(Oacc[nj][0] * inv0, Oacc[nj][1] * inv0, h0, lo0);
        split2(Oacc[nj][2] * inv1, Oacc[nj][3] * inv1, h1, lo1);
        *(uint32_t*)(Ch + tok0 * DM + col) = h0;
        *(uint32_t*)(Cl + tok0 * DM + col) = lo0;
        *(uint32_t*)(Ch + tok1 * DM + col) = h1;
        *(uint32_t*)(Cl + tok1 * DM + col) = lo1;
    }
}

// ---------------------------------------------------------------------------
extern "C" void kernel_launch(void* const* d_in, const int* in_sizes, int n_in,
                              void* d_out, int out_size)
{
    const float* x  = (const float*)d_in[0];
    const float* Wq = (const float*)d_in[1];
    const float* Wk = (const float*)d_in[2];
    const float* Wv = (const float*)d_in[3];
    const float* Wo = (const float*)d_in[4];
    const float* bo = (const float*)d_in[5];
    float* out = (float*)d_out;

    __nv_bfloat16 *xh, *xl, *qh, *ql, *kh, *kl, *vh, *vl, *ch, *cl, *wth, *wtl;
    cudaGetSymbolAddress((void**)&xh, g_xh);
    cudaGetSymbolAddress((void**)&xl, g_xl);
    cudaGetSymbolAddress((void**)&qh, g_qh);
    cudaGetSymbolAddress((void**)&ql, g_ql);
    cudaGetSymbolAddress((void**)&kh, g_kh);
    cudaGetSymbolAddress((void**)&kl, g_kl);
    cudaGetSymbolAddress((void**)&vh, g_vh);
    cudaGetSymbolAddress((void**)&vl, g_vl);
    cudaGetSymbolAddress((void**)&ch, g_ch);
    cudaGetSymbolAddress((void**)&cl, g_cl);
    cudaGetSymbolAddress((void**)&wth, g_wth);
    cudaGetSymbolAddress((void**)&wtl, g_wtl);

    static int attr_set = 0;
    if (!attr_set) {
        cudaFuncSetAttribute(gemm_hmma_kernel<true>,
                             cudaFuncAttributeMaxDynamicSharedMemorySize, GEMM_SMEM);
        cudaFuncSetAttribute(gemm_hmma_kernel<false>,
                             cudaFuncAttributeMaxDynamicSharedMemorySize, GEMM_SMEM);
        cudaFuncSetAttribute(attn_mma_kernel,
                             cudaFuncAttributeMaxDynamicSharedMemorySize, AT_SMEM);
        attr_set = 1;
    }

    const int n4 = Mrows * DM / 4;
    fsplit_kernel<<<(n4 + 255) / 256, 256>>>(x, xh, xl, n4);
    wsplit_kernel<<<dim3(32, 32, 4), 256>>>(Wq, Wk, Wv, Wo, wth, wtl);

    gemm_hmma_kernel<true><<<dim3(DM / 128, Mrows / 128, 3), 256, GEMM_SMEM>>>(
        xh, xl, wth, wtl, qh, ql, kh, kl, vh, vl, nullptr, nullptr);

    attn_mma_kernel<<<dim3(Sq / 128, Bsz * Hh), 256, AT_SMEM>>>(
        qh, ql, kh, kl, vh, vl, ch, cl);

    gemm_hmma_kernel<false><<<dim3(DM / 128, Mrows / 128, 1), 256, GEMM_SMEM>>>(
        ch, cl, wth + (size_t)3 * DM * DM, wtl + (size_t)3 * DM * DM,
        nullptr, nullptr, nullptr, nullptr, nullptr, nullptr, out, bo);
}